// round 1
// baseline (speedup 1.0000x reference)
#include <cuda_runtime.h>
#include <math.h>

// Problem constants (fixed by the reference)
#define NTOT   50000
#define NTYPE0 30000
#define ETOT   400000

// ---------------- static scratch (no runtime allocation allowed) ----------------
__device__ float g_bufA[NTOT * 256];
__device__ float g_bufB[NTOT * 256];
__device__ float g_feat[NTOT * 256];
__device__ float g_outb[NTOT * 256];
__device__ float g_el[NTOT * 4];
__device__ float g_er[NTOT * 4];
__device__ float g_den[NTOT * 4];
__device__ int   g_m[NTOT * 4];
__device__ float g_ex[ETOT * 4];

// ordered-int mapping so signed-int atomicMax works for floats (no NaNs here)
__device__ __forceinline__ int f2o(float f) {
    int i = __float_as_int(f);
    return i >= 0 ? i : (i ^ 0x7FFFFFFF);
}
__device__ __forceinline__ float o2f(int o) {
    int i = o >= 0 ? o : (o ^ 0x7FFFFFFF);
    return __int_as_float(i);
}

// ---------------- generic fp32 GEMM: C = A(MxK) @ B(KxN) (+bias) ----------------
// 64x64 tile, BK=16, 256 threads, 4x4 micro-tile per thread.
__global__ void gemm64(const float* __restrict__ A, const float* __restrict__ B,
                       const float* __restrict__ bias, float* __restrict__ C,
                       int M, int K, int N)
{
    __shared__ float As[16][65];   // transposed A tile, padded
    __shared__ float Bs[16][64];

    int tid = threadIdx.x;
    int rowBase = blockIdx.y * 64;
    int colBase = blockIdx.x * 64;
    int tx = tid & 15, ty = tid >> 4;

    int arow = tid >> 2;          // 0..63
    int acol = (tid & 3) << 2;    // 0,4,8,12
    int brow = tid >> 4;          // 0..15
    int bcol = (tid & 15) << 2;   // 0..60

    float acc[4][4];
#pragma unroll
    for (int i = 0; i < 4; i++)
#pragma unroll
        for (int j = 0; j < 4; j++) acc[i][j] = 0.f;

    for (int k0 = 0; k0 < K; k0 += 16) {
        float4 av = make_float4(0.f, 0.f, 0.f, 0.f);
        if (rowBase + arow < M)
            av = *reinterpret_cast<const float4*>(A + (size_t)(rowBase + arow) * K + k0 + acol);
        As[acol + 0][arow] = av.x;
        As[acol + 1][arow] = av.y;
        As[acol + 2][arow] = av.z;
        As[acol + 3][arow] = av.w;

        float4 bv = make_float4(0.f, 0.f, 0.f, 0.f);
        if (colBase + bcol < N)   // N is always a multiple of 4 here
            bv = *reinterpret_cast<const float4*>(B + (size_t)(k0 + brow) * N + colBase + bcol);
        *reinterpret_cast<float4*>(&Bs[brow][bcol]) = bv;

        __syncthreads();
#pragma unroll
        for (int k = 0; k < 16; k++) {
            float a0 = As[k][(ty << 2) + 0];
            float a1 = As[k][(ty << 2) + 1];
            float a2 = As[k][(ty << 2) + 2];
            float a3 = As[k][(ty << 2) + 3];
            float b0v = Bs[k][(tx << 2) + 0];
            float b1v = Bs[k][(tx << 2) + 1];
            float b2v = Bs[k][(tx << 2) + 2];
            float b3v = Bs[k][(tx << 2) + 3];
            acc[0][0] += a0 * b0v; acc[0][1] += a0 * b1v; acc[0][2] += a0 * b2v; acc[0][3] += a0 * b3v;
            acc[1][0] += a1 * b0v; acc[1][1] += a1 * b1v; acc[1][2] += a1 * b2v; acc[1][3] += a1 * b3v;
            acc[2][0] += a2 * b0v; acc[2][1] += a2 * b1v; acc[2][2] += a2 * b2v; acc[2][3] += a2 * b3v;
            acc[3][0] += a3 * b0v; acc[3][1] += a3 * b1v; acc[3][2] += a3 * b2v; acc[3][3] += a3 * b3v;
        }
        __syncthreads();
    }

#pragma unroll
    for (int i = 0; i < 4; i++) {
        int r = rowBase + (ty << 2) + i;
        if (r >= M) continue;
#pragma unroll
        for (int j = 0; j < 4; j++) {
            int c = colBase + (tx << 2) + j;
            if (c < N)
                C[(size_t)r * N + c] = acc[i][j] + (bias ? bias[c] : 0.f);
        }
    }
}

// ---------------- attention scores el/er + init of m/den --------------------
// one thread per (node, head)
__global__ void scores_init(const float* __restrict__ feat, const float* __restrict__ al,
                            const float* __restrict__ ar, float* __restrict__ el,
                            float* __restrict__ er, int* __restrict__ m,
                            float* __restrict__ den, int H, int D)
{
    int t = blockIdx.x * blockDim.x + threadIdx.x;
    if (t >= NTOT * H) return;
    int n = t / H, h = t % H;
    const float* f = feat + (size_t)n * H * D + h * D;
    const float* a = al + h * D;
    const float* b = ar + h * D;
    float sl = 0.f, sr = 0.f;
    for (int d = 0; d < D; d++) {
        float v = f[d];
        sl += v * a[d];
        sr += v * b[d];
    }
    el[t] = sl;
    er[t] = sr;
    m[t] = f2o(-INFINITY);
    den[t] = 0.f;
}

// ---------------- out initializers (residual + bias) ----------------
__global__ void set_bias_k(float* __restrict__ out, const float* __restrict__ bias, int hdmask)
{
    int t = blockIdx.x * blockDim.x + threadIdx.x;
    if (t >= NTOT * (hdmask + 1)) return;
    out[t] = bias[t & hdmask];
}

__global__ void set_res_bias_k(float* __restrict__ out, const float* __restrict__ h,
                               const float* __restrict__ bias, int hdmask)
{
    int t = blockIdx.x * blockDim.x + threadIdx.x;
    if (t >= NTOT * (hdmask + 1)) return;
    out[t] = h[t] + bias[t & hdmask];
}

// ---------------- edge kernels ----------------
__global__ void edge_max_k(const int* __restrict__ src, const int* __restrict__ dst,
                           const float* __restrict__ el, const float* __restrict__ er,
                           float* __restrict__ ebuf, int* __restrict__ m, int H)
{
    int e = blockIdx.x * blockDim.x + threadIdx.x;
    if (e >= ETOT) return;
    int s = src[e], d = dst[e];
#pragma unroll 4
    for (int h = 0; h < H; h++) {
        float x = el[s * H + h] + er[d * H + h];
        x = x > 0.f ? x : 0.2f * x;           // leaky relu slope 0.2
        ebuf[e * H + h] = x;
        atomicMax(&m[d * H + h], f2o(x));
    }
}

__global__ void edge_exp_k(const int* __restrict__ dst, const int* __restrict__ m,
                           float* __restrict__ ebuf, float* __restrict__ den, int H)
{
    int e = blockIdx.x * blockDim.x + threadIdx.x;
    if (e >= ETOT) return;
    int d = dst[e];
#pragma unroll 4
    for (int h = 0; h < H; h++) {
        float mm = o2f(m[d * H + h]);
        float x = expf(ebuf[e * H + h] - mm);
        ebuf[e * H + h] = x;
        atomicAdd(&den[d * H + h], x);
    }
}

__global__ void inv_k(float* __restrict__ den, int count)
{
    int t = blockIdx.x * blockDim.x + threadIdx.x;
    if (t >= count) return;
    float v = den[t];
    den[t] = v > 0.f ? 1.f / v : 0.f;
}

// one warp per edge; lanes stride over H*D features
__global__ void edge_aggr_k(const int* __restrict__ src, const int* __restrict__ dst,
                            const float* __restrict__ feat, const float* __restrict__ ex,
                            const float* __restrict__ invden, float* __restrict__ out,
                            int H, int dshift)
{
    int gt = blockIdx.x * blockDim.x + threadIdx.x;
    int e = gt >> 5;
    int lane = gt & 31;
    if (e >= ETOT) return;
    int s = src[e], d = dst[e];
    int HD = H << dshift;
    const float* fs = feat + (size_t)s * HD;
    float* od = out + (size_t)d * HD;
    for (int idx = lane; idx < HD; idx += 32) {
        int hh = idx >> dshift;
        float a = ex[e * H + hh] * invden[d * H + hh];
        atomicAdd(&od[idx], fs[idx] * a);
    }
}

// ---------------- combine: acc (+)= act(out) * mixweight ----------------
__global__ void combine_k(const float* __restrict__ out, float* __restrict__ acc,
                          const float* __restrict__ mixw, int l, int gi,
                          int hdshift, int doAct, int addFlag)
{
    int t = blockIdx.x * blockDim.x + threadIdx.x;
    if (t >= (NTOT << hdshift)) return;
    int n = t >> hdshift;
    int ty = (n < NTYPE0) ? 0 : 1;
    float m0 = mixw[ty * 6 + l * 2 + 0];
    float m1 = mixw[ty * 6 + l * 2 + 1];
    float mx = fmaxf(m0, m1);
    float e0 = expf(m0 - mx), e1 = expf(m1 - mx);
    float wv = ((gi == 0) ? e0 : e1) / (e0 + e1);
    float v = out[t];
    if (doAct) v = v > 0.f ? v : expm1f(v);   // elu
    float r = v * wv;
    if (addFlag) acc[t] += r; else acc[t] = r;
}

// ---------------- host orchestration ----------------
extern "C" void kernel_launch(void* const* d_in, const int* in_sizes, int n_in,
                              void* d_out, int out_size)
{
    const float* features0 = (const float*)d_in[0];
    const float* features1 = (const float*)d_in[1];
    const float* fc_w0 = (const float*)d_in[2];
    const float* fc_b0 = (const float*)d_in[3];
    const float* fc_w1 = (const float*)d_in[4];
    const float* fc_b1 = (const float*)d_in[5];
    const float* mix_w = (const float*)d_in[6];
    const float* W0  = (const float*)d_in[7];
    const float* al0 = (const float*)d_in[8];
    const float* ar0 = (const float*)d_in[9];
    const float* b0  = (const float*)d_in[10];
    const float* W1  = (const float*)d_in[11];
    const float* al1 = (const float*)d_in[12];
    const float* ar1 = (const float*)d_in[13];
    const float* b1  = (const float*)d_in[14];
    const float* W2  = (const float*)d_in[15];
    const float* al2 = (const float*)d_in[16];
    const float* ar2 = (const float*)d_in[17];
    const float* b2  = (const float*)d_in[18];
    const float* res2= (const float*)d_in[19];
    const int* srcs[2] = {(const int*)d_in[20], (const int*)d_in[22]};
    const int* dsts[2] = {(const int*)d_in[21], (const int*)d_in[23]};

    float *bufA, *bufB, *feat, *outb, *el, *er, *den, *ex;
    int* mb;
    cudaGetSymbolAddress((void**)&bufA, g_bufA);
    cudaGetSymbolAddress((void**)&bufB, g_bufB);
    cudaGetSymbolAddress((void**)&feat, g_feat);
    cudaGetSymbolAddress((void**)&outb, g_outb);
    cudaGetSymbolAddress((void**)&el,   g_el);
    cudaGetSymbolAddress((void**)&er,   g_er);
    cudaGetSymbolAddress((void**)&den,  g_den);
    cudaGetSymbolAddress((void**)&mb,   g_m);
    cudaGetSymbolAddress((void**)&ex,   g_ex);

    const int TPB = 256;
    const int N1n = NTOT - NTYPE0;

    // initial per-type FC -> h (N, 64), contiguous
    gemm64<<<dim3(1, (NTYPE0 + 63) / 64), TPB>>>(features0, fc_w0, fc_b0, bufA, NTYPE0, 128, 64);
    gemm64<<<dim3(1, (N1n + 63) / 64), TPB>>>(features1, fc_w1, fc_b1,
                                              bufA + (size_t)NTYPE0 * 64, N1n, 128, 64);

    float* h = bufA;
    float* acc = bufB;

    // layers 0 and 1 (H=4, D=64, HD=256)
    for (int l = 0; l < 2; l++) {
        int Kin = (l == 0) ? 64 : 256;
        const float* Wl  = (l == 0) ? W0 : W1;
        const float* all = (l == 0) ? al0 : al1;
        const float* arl = (l == 0) ? ar0 : ar1;
        const float* bl  = (l == 0) ? b0 : b1;
        for (int gi = 0; gi < 2; gi++) {
            gemm64<<<dim3(4, (NTOT + 63) / 64), TPB>>>(h, Wl + (size_t)gi * Kin * 256,
                                                       nullptr, feat, NTOT, Kin, 256);
            scores_init<<<(NTOT * 4 + TPB - 1) / TPB, TPB>>>(feat, all + gi * 256, arl + gi * 256,
                                                             el, er, mb, den, 4, 64);
            if (l == 0)
                set_bias_k<<<(NTOT * 256 + TPB - 1) / TPB, TPB>>>(outb, bl + gi * 256, 255);
            else
                set_res_bias_k<<<(NTOT * 256 + TPB - 1) / TPB, TPB>>>(outb, h, bl + gi * 256, 255);
            edge_max_k<<<(ETOT + TPB - 1) / TPB, TPB>>>(srcs[gi], dsts[gi], el, er, ex, mb, 4);
            edge_exp_k<<<(ETOT + TPB - 1) / TPB, TPB>>>(dsts[gi], mb, ex, den, 4);
            inv_k<<<(NTOT * 4 + TPB - 1) / TPB, TPB>>>(den, NTOT * 4);
            edge_aggr_k<<<(ETOT * 32 + TPB - 1) / TPB, TPB>>>(srcs[gi], dsts[gi], feat, ex, den,
                                                              outb, 4, 6);
            combine_k<<<(NTOT * 256 + TPB - 1) / TPB, TPB>>>(outb, acc, mix_w, l, gi, 8, 1, gi);
        }
        float* tmp = h; h = acc; acc = tmp;
    }

    // layer 2 (H=1, D=16), residual = h @ res2, no activation, outputs logits
    for (int gi = 0; gi < 2; gi++) {
        gemm64<<<dim3(1, (NTOT + 63) / 64), TPB>>>(h, W2 + (size_t)gi * 256 * 16,
                                                   nullptr, feat, NTOT, 256, 16);
        scores_init<<<(NTOT + TPB - 1) / TPB, TPB>>>(feat, al2 + gi * 16, ar2 + gi * 16,
                                                     el, er, mb, den, 1, 16);
        gemm64<<<dim3(1, (NTOT + 63) / 64), TPB>>>(h, res2 + (size_t)gi * 256 * 16,
                                                   b2 + gi * 16, outb, NTOT, 256, 16);
        edge_max_k<<<(ETOT + TPB - 1) / TPB, TPB>>>(srcs[gi], dsts[gi], el, er, ex, mb, 1);
        edge_exp_k<<<(ETOT + TPB - 1) / TPB, TPB>>>(dsts[gi], mb, ex, den, 1);
        inv_k<<<(NTOT + TPB - 1) / TPB, TPB>>>(den, NTOT);
        edge_aggr_k<<<(ETOT * 32 + TPB - 1) / TPB, TPB>>>(srcs[gi], dsts[gi], feat, ex, den,
                                                          outb, 1, 4);
        combine_k<<<(NTOT * 16 + TPB - 1) / TPB, TPB>>>(outb, (float*)d_out, mix_w, 2, gi, 4, 0, gi);
    }
}

// round 2
// speedup vs baseline: 1.3587x; 1.3587x over previous
#include <cuda_runtime.h>
#include <math.h>

#define NTOT   50000
#define NTYPE0 30000
#define ETOT   400000

// ---------------- static scratch ----------------
__device__ float g_h[NTOT * 256];
__device__ float g_acc[NTOT * 256];
__device__ float g_feat0[NTOT * 256];
__device__ float g_feat1[NTOT * 256];
__device__ float g_el[2][NTOT * 4];
__device__ float g_er[2][NTOT * 4];
__device__ float g_alpha[2][ETOT * 4];
__device__ float g_res[2][NTOT * 16];
__device__ int   g_rowptr[2][NTOT + 1];
__device__ int   g_cursor[2][NTOT];
__device__ int   g_counts[2][NTOT];
__device__ int   g_csrsrc[2][ETOT];

// ---------------- CSR build ----------------
__global__ void count_k(const int* __restrict__ dst, int* __restrict__ counts)
{
    int e = blockIdx.x * blockDim.x + threadIdx.x;
    if (e < ETOT) atomicAdd(&counts[dst[e]], 1);
}

// single-block exclusive scan of counts -> rowptr (+cursor copy)
__global__ void scan_k(const int* __restrict__ counts, int* __restrict__ rowptr,
                       int* __restrict__ cursor)
{
    __shared__ int warp_sums[32];
    __shared__ int s_carry;
    int tid = threadIdx.x, lane = tid & 31, wid = tid >> 5;
    int nw = blockDim.x >> 5;
    if (tid == 0) s_carry = 0;
    __syncthreads();
    for (int base = 0; base < NTOT; base += blockDim.x) {
        int i = base + tid;
        int v = (i < NTOT) ? counts[i] : 0;
        int x = v;
#pragma unroll
        for (int o = 1; o < 32; o <<= 1) {
            int y = __shfl_up_sync(~0u, x, o);
            if (lane >= o) x += y;
        }
        if (lane == 31) warp_sums[wid] = x;
        __syncthreads();
        if (wid == 0) {
            int s = (lane < nw) ? warp_sums[lane] : 0;
#pragma unroll
            for (int o = 1; o < 32; o <<= 1) {
                int y = __shfl_up_sync(~0u, s, o);
                if (lane >= o) s += y;
            }
            warp_sums[lane] = s;
        }
        __syncthreads();
        int woff = (wid == 0) ? 0 : warp_sums[wid - 1];
        int incl = x + woff;
        int excl = incl - v;
        int carry = s_carry;
        if (i < NTOT) { rowptr[i] = carry + excl; cursor[i] = carry + excl; }
        __syncthreads();
        if (tid == blockDim.x - 1) s_carry = carry + incl;
        __syncthreads();
    }
    if (tid == 0) rowptr[NTOT] = s_carry;
}

__global__ void scatter_k(const int* __restrict__ src, const int* __restrict__ dst,
                          int* __restrict__ cursor, int* __restrict__ csrsrc)
{
    int e = blockIdx.x * blockDim.x + threadIdx.x;
    if (e >= ETOT) return;
    int pos = atomicAdd(&cursor[dst[e]], 1);
    csrsrc[pos] = src[e];
}

// ---------------- GEMMs ----------------
// 64x64 tile fp32 GEMM (small-N cases)
__global__ void gemm64(const float* __restrict__ A, const float* __restrict__ B,
                       const float* __restrict__ bias, float* __restrict__ C,
                       int M, int K, int N)
{
    __shared__ float As[16][65];
    __shared__ float Bs[16][64];
    int tid = threadIdx.x;
    int rowBase = blockIdx.y * 64;
    int colBase = blockIdx.x * 64;
    int tx = tid & 15, ty = tid >> 4;
    int arow = tid >> 2, acol = (tid & 3) << 2;
    int brow = tid >> 4, bcol = (tid & 15) << 2;
    float acc[4][4];
#pragma unroll
    for (int i = 0; i < 4; i++)
#pragma unroll
        for (int j = 0; j < 4; j++) acc[i][j] = 0.f;
    for (int k0 = 0; k0 < K; k0 += 16) {
        float4 av = make_float4(0.f, 0.f, 0.f, 0.f);
        if (rowBase + arow < M)
            av = *reinterpret_cast<const float4*>(A + (size_t)(rowBase + arow) * K + k0 + acol);
        As[acol + 0][arow] = av.x; As[acol + 1][arow] = av.y;
        As[acol + 2][arow] = av.z; As[acol + 3][arow] = av.w;
        float4 bv = make_float4(0.f, 0.f, 0.f, 0.f);
        if (colBase + bcol < N)
            bv = *reinterpret_cast<const float4*>(B + (size_t)(k0 + brow) * N + colBase + bcol);
        *reinterpret_cast<float4*>(&Bs[brow][bcol]) = bv;
        __syncthreads();
#pragma unroll
        for (int k = 0; k < 16; k++) {
            float a0 = As[k][(ty << 2) + 0], a1 = As[k][(ty << 2) + 1];
            float a2 = As[k][(ty << 2) + 2], a3 = As[k][(ty << 2) + 3];
            float b0v = Bs[k][(tx << 2) + 0], b1v = Bs[k][(tx << 2) + 1];
            float b2v = Bs[k][(tx << 2) + 2], b3v = Bs[k][(tx << 2) + 3];
            acc[0][0] += a0 * b0v; acc[0][1] += a0 * b1v; acc[0][2] += a0 * b2v; acc[0][3] += a0 * b3v;
            acc[1][0] += a1 * b0v; acc[1][1] += a1 * b1v; acc[1][2] += a1 * b2v; acc[1][3] += a1 * b3v;
            acc[2][0] += a2 * b0v; acc[2][1] += a2 * b1v; acc[2][2] += a2 * b2v; acc[2][3] += a2 * b3v;
            acc[3][0] += a3 * b0v; acc[3][1] += a3 * b1v; acc[3][2] += a3 * b2v; acc[3][3] += a3 * b3v;
        }
        __syncthreads();
    }
#pragma unroll
    for (int i = 0; i < 4; i++) {
        int r = rowBase + (ty << 2) + i;
        if (r >= M) continue;
#pragma unroll
        for (int j = 0; j < 4; j++) {
            int c = colBase + (tx << 2) + j;
            if (c < N) C[(size_t)r * N + c] = acc[i][j] + (bias ? bias[c] : 0.f);
        }
    }
}

// 128x128 tile, 8x8 microtile, 256 threads. Requires N % 128 == 0, K % 8 == 0.
__global__ void __launch_bounds__(256, 2)
gemm128(const float* __restrict__ A, const float* __restrict__ B,
        float* __restrict__ C, int M, int K, int N)
{
    __shared__ float As[8][132];
    __shared__ float Bs[8][128];
    int tid = threadIdx.x;
    int rb = blockIdx.y * 128, cb = blockIdx.x * 128;
    int tx = tid & 15, ty = tid >> 4;
    int arow = tid >> 1, acol = (tid & 1) << 2;
    int brow = tid >> 5, bcol = (tid & 31) << 2;

    float acc[8][8];
#pragma unroll
    for (int i = 0; i < 8; i++)
#pragma unroll
        for (int j = 0; j < 8; j++) acc[i][j] = 0.f;

    for (int k0 = 0; k0 < K; k0 += 8) {
        float4 av = make_float4(0.f, 0.f, 0.f, 0.f);
        if (rb + arow < M)
            av = *reinterpret_cast<const float4*>(A + (size_t)(rb + arow) * K + k0 + acol);
        As[acol + 0][arow] = av.x; As[acol + 1][arow] = av.y;
        As[acol + 2][arow] = av.z; As[acol + 3][arow] = av.w;
        float4 bv = *reinterpret_cast<const float4*>(B + (size_t)(k0 + brow) * N + cb + bcol);
        *reinterpret_cast<float4*>(&Bs[brow][bcol]) = bv;
        __syncthreads();
#pragma unroll
        for (int k = 0; k < 8; k++) {
            float a[8], b[8];
            *reinterpret_cast<float4*>(a)     = *reinterpret_cast<float4*>(&As[k][ty * 8]);
            *reinterpret_cast<float4*>(a + 4) = *reinterpret_cast<float4*>(&As[k][ty * 8 + 4]);
            *reinterpret_cast<float4*>(b)     = *reinterpret_cast<float4*>(&Bs[k][tx * 4]);
            *reinterpret_cast<float4*>(b + 4) = *reinterpret_cast<float4*>(&Bs[k][64 + tx * 4]);
#pragma unroll
            for (int i = 0; i < 8; i++)
#pragma unroll
                for (int j = 0; j < 8; j++) acc[i][j] += a[i] * b[j];
        }
        __syncthreads();
    }
#pragma unroll
    for (int i = 0; i < 8; i++) {
        int r = rb + ty * 8 + i;
        if (r >= M) continue;
        float4 v0 = make_float4(acc[i][0], acc[i][1], acc[i][2], acc[i][3]);
        float4 v1 = make_float4(acc[i][4], acc[i][5], acc[i][6], acc[i][7]);
        *reinterpret_cast<float4*>(C + (size_t)r * N + cb + tx * 4) = v0;
        *reinterpret_cast<float4*>(C + (size_t)r * N + cb + 64 + tx * 4) = v1;
    }
}

// ---------------- attention scores: warp per (node, head) ----------------
__global__ void scores_k(const float* __restrict__ feat, const float* __restrict__ al,
                         const float* __restrict__ ar, float* __restrict__ el,
                         float* __restrict__ er, int H, int D)
{
    int n = blockIdx.x;
    int wid = threadIdx.x >> 5;
    int lane = threadIdx.x & 31;
    const float* f = feat + (size_t)n * H * D + wid * D;
    float sl = 0.f, sr = 0.f;
    for (int d = lane; d < D; d += 32) {
        float v = f[d];
        sl += v * al[wid * D + d];
        sr += v * ar[wid * D + d];
    }
#pragma unroll
    for (int o = 16; o > 0; o >>= 1) {
        sl += __shfl_down_sync(~0u, sl, o);
        sr += __shfl_down_sync(~0u, sr, o);
    }
    if (lane == 0) { el[n * H + wid] = sl; er[n * H + wid] = sr; }
}

// ---------------- edge softmax (CSR, warp per dst node) ----------------
template <int H>
__global__ void softmax_k(const int* __restrict__ rowptr, const int* __restrict__ csrsrc,
                          const float* __restrict__ el, const float* __restrict__ er,
                          float* __restrict__ alpha)
{
    int n = blockIdx.x * (blockDim.x >> 5) + (threadIdx.x >> 5);
    int lane = threadIdx.x & 31;
    if (n >= NTOT) return;
    int beg = rowptr[n], end = rowptr[n + 1];
    if (beg == end) return;

    float erh[H];
#pragma unroll
    for (int h = 0; h < H; h++) erh[h] = er[n * H + h];

    float mx[H];
#pragma unroll
    for (int h = 0; h < H; h++) mx[h] = -1e30f;

    for (int p = beg + lane; p < end; p += 32) {
        int s = csrsrc[p];
#pragma unroll
        for (int h = 0; h < H; h++) {
            float e = el[s * H + h] + erh[h];
            e = e > 0.f ? e : 0.2f * e;
            alpha[p * H + h] = e;
            mx[h] = fmaxf(mx[h], e);
        }
    }
#pragma unroll
    for (int h = 0; h < H; h++)
#pragma unroll
        for (int o = 16; o > 0; o >>= 1)
            mx[h] = fmaxf(mx[h], __shfl_xor_sync(~0u, mx[h], o));

    float den[H];
#pragma unroll
    for (int h = 0; h < H; h++) den[h] = 0.f;
    for (int p = beg + lane; p < end; p += 32) {
#pragma unroll
        for (int h = 0; h < H; h++) {
            float x = expf(alpha[p * H + h] - mx[h]);
            alpha[p * H + h] = x;
            den[h] += x;
        }
    }
#pragma unroll
    for (int h = 0; h < H; h++)
#pragma unroll
        for (int o = 16; o > 0; o >>= 1)
            den[h] += __shfl_xor_sync(~0u, den[h], o);

    float inv[H];
#pragma unroll
    for (int h = 0; h < H; h++) inv[h] = 1.f / den[h];
    for (int p = beg + lane; p < end; p += 32) {
#pragma unroll
        for (int h = 0; h < H; h++) alpha[p * H + h] *= inv[h];
    }
}

// ---------------- fused dual-graph aggregation + epilogue (HD=256) ----------------
// block = 256 threads = one dst node; thread owns one of the 256 feature dims
__global__ void aggr256_k(const int* __restrict__ rp0, const int* __restrict__ cs0,
                          const float* __restrict__ a0, const float* __restrict__ f0,
                          const int* __restrict__ rp1, const int* __restrict__ cs1,
                          const float* __restrict__ a1, const float* __restrict__ f1,
                          const float* __restrict__ h, const float* __restrict__ bias0,
                          const float* __restrict__ bias1, const float* __restrict__ mixw,
                          int layer, int useRes, float* __restrict__ out)
{
    int n = blockIdx.x;
    int d = threadIdx.x;
    int head = d >> 6;

    float acc0 = 0.f, acc1 = 0.f;
    int b = rp0[n], e = rp0[n + 1];
    for (int p = b; p < e; p++) {
        int s = __ldg(&cs0[p]);
        float a = __ldg(&a0[p * 4 + head]);
        acc0 += f0[(size_t)s * 256 + d] * a;
    }
    b = rp1[n]; e = rp1[n + 1];
    for (int p = b; p < e; p++) {
        int s = __ldg(&cs1[p]);
        float a = __ldg(&a1[p * 4 + head]);
        acc1 += f1[(size_t)s * 256 + d] * a;
    }

    float res = useRes ? h[(size_t)n * 256 + d] : 0.f;
    float v0 = acc0 + res + bias0[d];
    float v1 = acc1 + res + bias1[d];
    v0 = v0 > 0.f ? v0 : expm1f(v0);
    v1 = v1 > 0.f ? v1 : expm1f(v1);

    int ty = (n < NTYPE0) ? 0 : 1;
    float m0 = mixw[ty * 6 + layer * 2 + 0];
    float m1 = mixw[ty * 6 + layer * 2 + 1];
    float mxw = fmaxf(m0, m1);
    float e0 = expf(m0 - mxw), e1 = expf(m1 - mxw);
    float inv = 1.f / (e0 + e1);
    out[(size_t)n * 256 + d] = v0 * (e0 * inv) + v1 * (e1 * inv);
}

// ---------------- layer 2 aggregation (H=1, D=16) ----------------
// 256 threads handle 16 nodes x 16 dims
__global__ void aggr16_k(const int* __restrict__ rp0, const int* __restrict__ cs0,
                         const float* __restrict__ a0, const float* __restrict__ f0,
                         const int* __restrict__ rp1, const int* __restrict__ cs1,
                         const float* __restrict__ a1, const float* __restrict__ f1,
                         const float* __restrict__ res0, const float* __restrict__ res1,
                         const float* __restrict__ mixw, float* __restrict__ logits)
{
    int n = blockIdx.x * 16 + (threadIdx.x >> 4);
    int d = threadIdx.x & 15;
    if (n >= NTOT) return;

    float acc0 = 0.f, acc1 = 0.f;
    int b = rp0[n], e = rp0[n + 1];
    for (int p = b; p < e; p++)
        acc0 += f0[(size_t)__ldg(&cs0[p]) * 16 + d] * __ldg(&a0[p]);
    b = rp1[n]; e = rp1[n + 1];
    for (int p = b; p < e; p++)
        acc1 += f1[(size_t)__ldg(&cs1[p]) * 16 + d] * __ldg(&a1[p]);

    float v0 = acc0 + res0[(size_t)n * 16 + d];
    float v1 = acc1 + res1[(size_t)n * 16 + d];

    int ty = (n < NTYPE0) ? 0 : 1;
    float m0 = mixw[ty * 6 + 2 * 2 + 0];
    float m1 = mixw[ty * 6 + 2 * 2 + 1];
    float mxw = fmaxf(m0, m1);
    float e0 = expf(m0 - mxw), e1 = expf(m1 - mxw);
    float inv = 1.f / (e0 + e1);
    logits[(size_t)n * 16 + d] = v0 * (e0 * inv) + v1 * (e1 * inv);
}

// ---------------- host orchestration ----------------
extern "C" void kernel_launch(void* const* d_in, const int* in_sizes, int n_in,
                              void* d_out, int out_size)
{
    const float* features0 = (const float*)d_in[0];
    const float* features1 = (const float*)d_in[1];
    const float* fc_w0 = (const float*)d_in[2];
    const float* fc_b0 = (const float*)d_in[3];
    const float* fc_w1 = (const float*)d_in[4];
    const float* fc_b1 = (const float*)d_in[5];
    const float* mix_w = (const float*)d_in[6];
    const float* W0  = (const float*)d_in[7];
    const float* al0 = (const float*)d_in[8];
    const float* ar0 = (const float*)d_in[9];
    const float* b0  = (const float*)d_in[10];
    const float* W1  = (const float*)d_in[11];
    const float* al1 = (const float*)d_in[12];
    const float* ar1 = (const float*)d_in[13];
    const float* b1  = (const float*)d_in[14];
    const float* W2  = (const float*)d_in[15];
    const float* al2 = (const float*)d_in[16];
    const float* ar2 = (const float*)d_in[17];
    const float* b2  = (const float*)d_in[18];
    const float* res2= (const float*)d_in[19];
    const int* srcs[2] = {(const int*)d_in[20], (const int*)d_in[22]};
    const int* dsts[2] = {(const int*)d_in[21], (const int*)d_in[23]};

    float *h, *acc, *feat[2], *elp, *erp, *alphap, *resp;
    int *rowptrp, *cursorp, *countsp, *csrsrcp;
    cudaGetSymbolAddress((void**)&h,    g_h);
    cudaGetSymbolAddress((void**)&acc,  g_acc);
    cudaGetSymbolAddress((void**)&feat[0], g_feat0);
    cudaGetSymbolAddress((void**)&feat[1], g_feat1);
    cudaGetSymbolAddress((void**)&elp,  g_el);
    cudaGetSymbolAddress((void**)&erp,  g_er);
    cudaGetSymbolAddress((void**)&alphap, g_alpha);
    cudaGetSymbolAddress((void**)&resp, g_res);
    cudaGetSymbolAddress((void**)&rowptrp, g_rowptr);
    cudaGetSymbolAddress((void**)&cursorp, g_cursor);
    cudaGetSymbolAddress((void**)&countsp, g_counts);
    cudaGetSymbolAddress((void**)&csrsrcp, g_csrsrc);

    float* el[2]   = {elp, elp + NTOT * 4};
    float* er[2]   = {erp, erp + NTOT * 4};
    float* alpha[2]= {alphap, alphap + ETOT * 4};
    float* res[2]  = {resp, resp + NTOT * 16};
    int* rowptr[2] = {rowptrp, rowptrp + NTOT + 1};
    int* cursor[2] = {cursorp, cursorp + NTOT};
    int* counts[2] = {countsp, countsp + NTOT};
    int* csrsrc[2] = {csrsrcp, csrsrcp + ETOT};

    const int TPB = 256;
    const int N1n = NTOT - NTYPE0;
    const int EB = (ETOT + TPB - 1) / TPB;

    // ---- build CSR for both graphs (reused by all 3 layers) ----
    for (int gi = 0; gi < 2; gi++) {
        cudaMemsetAsync(counts[gi], 0, NTOT * sizeof(int));
        count_k<<<EB, TPB>>>(dsts[gi], counts[gi]);
        scan_k<<<1, 1024>>>(counts[gi], rowptr[gi], cursor[gi]);
        scatter_k<<<EB, TPB>>>(srcs[gi], dsts[gi], cursor[gi], csrsrc[gi]);
    }

    // ---- input per-type FC -> h (N, 64) ----
    gemm64<<<dim3(1, (NTYPE0 + 63) / 64), TPB>>>(features0, fc_w0, fc_b0, h, NTYPE0, 128, 64);
    gemm64<<<dim3(1, (N1n + 63) / 64), TPB>>>(features1, fc_w1, fc_b1,
                                              h + (size_t)NTYPE0 * 64, N1n, 128, 64);

    // ---- layers 0 and 1 (H=4, D=64, HD=256) ----
    float* cur = h;
    float* nxt = acc;
    for (int l = 0; l < 2; l++) {
        int Kin = (l == 0) ? 64 : 256;
        const float* Wl  = (l == 0) ? W0 : W1;
        const float* all = (l == 0) ? al0 : al1;
        const float* arl = (l == 0) ? ar0 : ar1;
        const float* bl  = (l == 0) ? b0 : b1;
        for (int gi = 0; gi < 2; gi++) {
            gemm128<<<dim3(2, (NTOT + 127) / 128), 256>>>(cur, Wl + (size_t)gi * Kin * 256,
                                                          feat[gi], NTOT, Kin, 256);
            scores_k<<<NTOT, 128>>>(feat[gi], all + gi * 256, arl + gi * 256,
                                    el[gi], er[gi], 4, 64);
            softmax_k<4><<<(NTOT + 7) / 8, 256>>>(rowptr[gi], csrsrc[gi], el[gi], er[gi], alpha[gi]);
        }
        aggr256_k<<<NTOT, 256>>>(rowptr[0], csrsrc[0], alpha[0], feat[0],
                                 rowptr[1], csrsrc[1], alpha[1], feat[1],
                                 cur, bl, bl + 256, mix_w, l, (l == 1) ? 1 : 0, nxt);
        float* t = cur; cur = nxt; nxt = t;
    }

    // ---- layer 2 (H=1, D=16): feat + residual GEMMs, softmax, aggregate ----
    for (int gi = 0; gi < 2; gi++) {
        gemm64<<<dim3(1, (NTOT + 63) / 64), TPB>>>(cur, W2 + (size_t)gi * 256 * 16,
                                                   nullptr, feat[gi], NTOT, 256, 16);
        gemm64<<<dim3(1, (NTOT + 63) / 64), TPB>>>(cur, res2 + (size_t)gi * 256 * 16,
                                                   b2 + gi * 16, res[gi], NTOT, 256, 16);
        scores_k<<<NTOT, 32>>>(feat[gi], al2 + gi * 16, ar2 + gi * 16, el[gi], er[gi], 1, 16);
        softmax_k<1><<<(NTOT + 7) / 8, 256>>>(rowptr[gi], csrsrc[gi], el[gi], er[gi], alpha[gi]);
    }
    aggr16_k<<<(NTOT + 15) / 16, 256>>>(rowptr[0], csrsrc[0], alpha[0], feat[0],
                                        rowptr[1], csrsrc[1], alpha[1], feat[1],
                                        res[0], res[1], mix_w, (float*)d_out);
}